// round 9
// baseline (speedup 1.0000x reference)
#include <cuda_runtime.h>

#define GN 4096   // N*N
#define TT 168    // T
#define BB 128    // B
#define NN 64     // N
#define PP 128    // P

#define ROWS_PER_BLK 8
#define MV_BLOCKS (GN / ROWS_PER_BLK)      // 512
#define TOTAL_BLK (BB + MV_BLOCKS)         // 128 y-blocks first, then 512 matvec
#define GROUPS    (GN / NN)                // 64 i-groups, 8 matvec blocks each
#define CNT_PAD   32                       // 128-byte stride between counters

// Scratch + sync (allocation-free rule: __device__ globals; zero at load,
// self-resetting each replay)
__device__ float d_v[GN];
__device__ float d_y[BB * NN];             // y[b*64 + j]
__device__ int   d_cnt[GROUPS * CNT_PAD];  // per-group arrival counters (padded)
__device__ int   d_y_done;
__device__ int   d_tail_done;

__device__ __forceinline__ float dot4(float4 a, float4 b) {
    return a.x * b.x + a.y * b.y + a.z * b.z + a.w * b.w;
}

// ---------------------------------------------------------------------------
// Single fused kernel, hierarchical completion (no hot-spot atomics):
//  blocks [0, 128):   y-block b: y[b,j] = sum_p x[b,j,p]*alpha[x_i[b,p]];
//                     fence; count into d_y_done. (DRAM-bound, ~2us)
//  blocks [128, 640): matvec block m: rows 8m..8m+7 (group i = m>>3... rows
//                     share i = row>>6 across 8 consecutive blocks).
//                     w^2 staged in smem, warp-per-row dot from L2, fused
//                     F epilogue, store d_v, fence, count into d_cnt[i].
//                     The 8th arriver of group i computes Z[:, i] from the
//                     group's 64 v values + y — overlapped with other
//                     groups' matvec work. Tail ~0.3us, contention-free.
// ---------------------------------------------------------------------------
__global__ void __launch_bounds__(256) k_fused(const float* __restrict__ g,
                                               const float* __restrict__ w,
                                               const float* __restrict__ alphas,
                                               const float* __restrict__ x,
                                               const int*   __restrict__ xi,
                                               float* __restrict__ Fout,
                                               float* __restrict__ Zout) {
    __shared__ __align__(16) float ws[GN];   // matvec: w^2 | y-block: ap reuse
    __shared__ float sal[TT];
    __shared__ __align__(16) float sv[NN];   // tail: group's v values
    __shared__ int sh_old;

    const int blk  = blockIdx.x;
    const int tid  = threadIdx.x;
    const int wid  = tid >> 5;
    const int lane = tid & 31;

    if (blk < BB) {
        // ---------------- y-block for batch b ----------------
        const int b = blk;
        float* ap = ws;
        if (tid < PP)
            ap[tid] = alphas[xi[b * PP + tid]];
        __syncthreads();

        #pragma unroll
        for (int j = wid; j < NN; j += 8) {
            const float* __restrict__ xr = x + ((size_t)b * NN + j) * PP;
            float s = xr[lane]      * ap[lane]
                    + xr[lane + 32] * ap[lane + 32]
                    + xr[lane + 64] * ap[lane + 64]
                    + xr[lane + 96] * ap[lane + 96];
            #pragma unroll
            for (int o = 16; o > 0; o >>= 1)
                s += __shfl_xor_sync(0xffffffffu, s, o);
            if (lane == 0) d_y[b * NN + j] = s;
        }
        __syncthreads();
        if (tid == 0) {
            __threadfence();
            atomicAdd(&d_y_done, 1);
        }
        return;
    }

    // ---------------- matvec block m ----------------
    const int m  = blk - BB;
    const int gi = m >> 3;                   // i-group (rows gi*64 .. gi*64+63)

    // stage w^2 (16 KB) + alphas into smem
    const float4* __restrict__ w4g = reinterpret_cast<const float4*>(w);
    float4* ws4 = reinterpret_cast<float4*>(ws);
    #pragma unroll
    for (int k = 0; k < 4; k++) {
        float4 t = w4g[tid + k * 256];
        t.x *= t.x; t.y *= t.y; t.z *= t.z; t.w *= t.w;
        ws4[tid + k * 256] = t;
    }
    if (tid < TT) sal[tid] = alphas[tid];
    __syncthreads();

    // warp-per-row dot product (row = 8m + wid)
    const int row = m * ROWS_PER_BLK + wid;
    const float4* __restrict__ g4 =
        reinterpret_cast<const float4*>(g + (size_t)row * GN);

    float acc0 = 0.f, acc1 = 0.f, acc2 = 0.f, acc3 = 0.f;
    #pragma unroll
    for (int c = 0; c < 8; c++) {
        const int base = c * 128 + lane;              // float4 units
        float4 a0 = g4[base];       float4 a1 = g4[base + 32];
        float4 a2 = g4[base + 64];  float4 a3 = g4[base + 96];
        float4 b0 = ws4[base];      float4 b1 = ws4[base + 32];
        float4 b2 = ws4[base + 64]; float4 b3 = ws4[base + 96];
        acc0 += dot4(a0, b0);
        acc1 += dot4(a1, b1);
        acc2 += dot4(a2, b2);
        acc3 += dot4(a3, b3);
    }
    float s = (acc0 + acc1) + (acc2 + acc3);
    #pragma unroll
    for (int o = 16; o > 0; o >>= 1)
        s += __shfl_xor_sync(0xffffffffu, s, o);       // all lanes get sum

    if (lane == 0) d_v[row] = s;

    // F epilogue: F[row, t] = v * alpha[t]
    float* __restrict__ Frow = Fout + (size_t)row * TT;
    #pragma unroll
    for (int t = lane; t < TT; t += 32)
        Frow[t] = s * sal[t];

    // publish d_v, then count into this group's padded counter
    if (lane == 0) __threadfence();
    __syncthreads();
    if (tid == 0)
        sh_old = atomicAdd(&d_cnt[gi * CNT_PAD], 1);
    __syncthreads();
    if (sh_old != ROWS_PER_BLK - 1)
        return;                                        // not last of group

    // ---------------- group tail: compute Z[:, gi] ----------------
    // gate on y (128 y-blocks finished ~5us ago; poll passes immediately)
    if (tid == 0) {
        while (atomicAdd(&d_y_done, 0) < BB)
            __nanosleep(32);
        __threadfence();
    }
    __syncthreads();

    // group's 64 v values (L2-hot) into smem
    if (tid < NN)
        sv[tid] = __ldcg(&d_v[gi * NN + tid]);
    __syncthreads();

    // thread (b = tid>>1, h = tid&1): half-dot over j in [h*32, h*32+32)
    {
        const int b = tid >> 1;
        const int h = tid & 1;
        const float4* __restrict__ y4 =
            reinterpret_cast<const float4*>(d_y + b * NN + h * 32);
        const float4* __restrict__ v4 =
            reinterpret_cast<const float4*>(sv + h * 32);

        float4 a0 = y4[0]; float4 a1 = y4[1]; float4 a2 = y4[2]; float4 a3 = y4[3];
        float4 a4 = y4[4]; float4 a5 = y4[5]; float4 a6 = y4[6]; float4 a7 = y4[7];
        float t0 = dot4(a0, v4[0]) + dot4(a1, v4[1])
                 + dot4(a2, v4[2]) + dot4(a3, v4[3]);
        float t1 = dot4(a4, v4[4]) + dot4(a5, v4[5])
                 + dot4(a6, v4[6]) + dot4(a7, v4[7]);
        float zs = t0 + t1;
        zs += __shfl_xor_sync(0xffffffffu, zs, 1);
        if (h == 0)
            Zout[b * NN + gi] = zs;
    }

    // reset this group's counter; last tail resets globals (next replay)
    if (tid == 0) {
        atomicExch(&d_cnt[gi * CNT_PAD], 0);
        if (atomicAdd(&d_tail_done, 1) == GROUPS - 1) {
            atomicExch(&d_tail_done, 0);
            atomicExch(&d_y_done, 0);
        }
    }
}

// ---------------------------------------------------------------------------
extern "C" void kernel_launch(void* const* d_in, const int* in_sizes, int n_in,
                              void* d_out, int out_size) {
    const float* x      = (const float*)d_in[0];   // [B, N, P]
    const int*   xi     = (const int*)  d_in[1];   // [B, P]
    const float* g      = (const float*)d_in[2];   // [N*N, N*N]
    const float* w      = (const float*)d_in[3];   // [N*N, 1]
    const float* alphas = (const float*)d_in[4];   // [1, T]

    float* out = (float*)d_out;
    float* Z = out;               // [B, N]   = 8192
    float* F = out + BB * NN;     // [N*N, T] = 688128

    k_fused<<<TOTAL_BLK, 256>>>(g, w, alphas, x, xi, F, Z);
}

// round 10
// speedup vs baseline: 1.4800x; 1.4800x over previous
#include <cuda_runtime.h>

#define GN 4096   // N*N
#define TT 168    // T
#define BB 128    // B
#define NN 64     // N
#define PP 128    // P

#define ROWS_PER_BLK 8
#define MV_BLOCKS (GN / ROWS_PER_BLK)      // 512
#define Y_BLOCKS  (BB / 2)                 // 64 (2 batches per block)
#define TOTAL_K1  (MV_BLOCKS + Y_BLOCKS)   // 576

// Scratch (allocation-free rule: __device__ globals)
__device__ float d_v[GN];
__device__ float d_y[BB * NN];

__device__ __forceinline__ float dot4(float4 a, float4 b) {
    return a.x * b.x + a.y * b.y + a.z * b.z + a.w * b.w;
}

// ---------------------------------------------------------------------------
// Kernel 1 (512 threads = 16 warps per block -> 9216 warps chip-wide, ~97%
// of warp slots, vs 43% with warp-per-row):
//  blocks [0, 512):  matvec, 8 rows/block, TWO warps per row (k-halves),
//                    w^2 staged in smem once per block (w traffic stays 8MB).
//                    Partials combined via smem; fused F epilogue.
//  blocks [512, 576): y for 2 batches: y[b,j] = sum_p x[b,j,p]*alpha[xi[b,p]].
// ---------------------------------------------------------------------------
__global__ void __launch_bounds__(512) k_main(const float* __restrict__ g,
                                              const float* __restrict__ w,
                                              const float* __restrict__ alphas,
                                              const float* __restrict__ x,
                                              const int*   __restrict__ xi,
                                              float* __restrict__ Fout) {
    __shared__ __align__(16) float ws[GN];   // matvec: w^2 | y-block: ap reuse
    __shared__ float sal[TT];
    __shared__ float sp[16];

    const int blk  = blockIdx.x;
    const int tid  = threadIdx.x;
    const int wid  = tid >> 5;
    const int lane = tid & 31;

    if (blk < MV_BLOCKS) {
        // ---- stage w^2 (16 KB) + alphas into smem ----
        const float4* __restrict__ w4g = reinterpret_cast<const float4*>(w);
        float4* ws4 = reinterpret_cast<float4*>(ws);
        #pragma unroll
        for (int k = 0; k < 2; k++) {
            float4 t = w4g[tid + k * 512];
            t.x *= t.x; t.y *= t.y; t.z *= t.z; t.w *= t.w;
            ws4[tid + k * 512] = t;
        }
        if (tid < TT) sal[tid] = alphas[tid];
        __syncthreads();

        // ---- two warps per row: warp handles k-half h of row rl ----
        const int rl  = wid >> 1;            // row-local 0..7
        const int h   = wid & 1;             // k-half
        const int row = blk * ROWS_PER_BLK + rl;
        const float4* __restrict__ g4 =
            reinterpret_cast<const float4*>(g + (size_t)row * GN);

        float acc0 = 0.f, acc1 = 0.f, acc2 = 0.f, acc3 = 0.f;
        #pragma unroll
        for (int c = 0; c < 4; c++) {
            const int base = h * 512 + c * 128 + lane;    // float4 units
            float4 a0 = g4[base];       float4 a1 = g4[base + 32];
            float4 a2 = g4[base + 64];  float4 a3 = g4[base + 96];
            float4 b0 = ws4[base];      float4 b1 = ws4[base + 32];
            float4 b2 = ws4[base + 64]; float4 b3 = ws4[base + 96];
            acc0 += dot4(a0, b0);
            acc1 += dot4(a1, b1);
            acc2 += dot4(a2, b2);
            acc3 += dot4(a3, b3);
        }
        float s = (acc0 + acc1) + (acc2 + acc3);
        #pragma unroll
        for (int o = 16; o > 0; o >>= 1)
            s += __shfl_xor_sync(0xffffffffu, s, o);
        if (lane == 0) sp[wid] = s;
        __syncthreads();

        // ---- warp wid (<8) finalizes row blk*8+wid: v store + F epilogue ----
        if (wid < ROWS_PER_BLK) {
            const float v = sp[2 * wid] + sp[2 * wid + 1];
            const int r = blk * ROWS_PER_BLK + wid;
            if (lane == 0) d_v[r] = v;
            float* __restrict__ Frow = Fout + (size_t)r * TT;
            #pragma unroll
            for (int t = lane; t < TT; t += 32)
                Frow[t] = v * sal[t];
        }
    } else {
        // ---- y-block: batches b0, b0+1 ----
        const int b0 = (blk - MV_BLOCKS) * 2;
        float* ap = ws;   // reuse smem: ap[0..127] batch b0, ap[128..255] b0+1
        if (tid < 2 * PP)
            ap[tid] = alphas[xi[b0 * PP + tid]];
        __syncthreads();

        const int bsel = wid >> 3;           // 0 or 1
        const int b    = b0 + bsel;
        const int w8   = wid & 7;
        const float* __restrict__ apb = ap + bsel * PP;
        #pragma unroll
        for (int j = w8; j < NN; j += 8) {
            const float* __restrict__ xr = x + ((size_t)b * NN + j) * PP;
            float s = xr[lane]      * apb[lane]
                    + xr[lane + 32] * apb[lane + 32]
                    + xr[lane + 64] * apb[lane + 64]
                    + xr[lane + 96] * apb[lane + 96];
            #pragma unroll
            for (int o = 16; o > 0; o >>= 1)
                s += __shfl_xor_sync(0xffffffffu, s, o);
            if (lane == 0) d_y[b * NN + j] = s;
        }
    }
}

// ---------------------------------------------------------------------------
// Kernel 2: Z[b,i] = sum_j v[i*64+j] * y[b,j]
// grid 128, one output per 4-thread quad, all 8 float4 loads independent.
// ---------------------------------------------------------------------------
__global__ void __launch_bounds__(256) k_z(float* __restrict__ Zout) {
    const int b   = blockIdx.x;
    const int tid = threadIdx.x;
    const int i   = tid >> 2;      // output row 0..63
    const int q   = tid & 3;       // j-segment 0..3

    const float4* __restrict__ v4 =
        reinterpret_cast<const float4*>(d_v) + i * 16 + q * 4;
    const float4* __restrict__ y4 =
        reinterpret_cast<const float4*>(d_y) + b * 16 + q * 4;

    float4 a0 = v4[0]; float4 a1 = v4[1]; float4 a2 = v4[2]; float4 a3 = v4[3];
    float4 b0 = y4[0]; float4 b1 = y4[1]; float4 b2 = y4[2]; float4 b3 = y4[3];

    float s = (dot4(a0, b0) + dot4(a1, b1)) + (dot4(a2, b2) + dot4(a3, b3));
    s += __shfl_xor_sync(0xffffffffu, s, 1);
    s += __shfl_xor_sync(0xffffffffu, s, 2);

    if (q == 0)
        Zout[b * NN + i] = s;
}

// ---------------------------------------------------------------------------
extern "C" void kernel_launch(void* const* d_in, const int* in_sizes, int n_in,
                              void* d_out, int out_size) {
    const float* x      = (const float*)d_in[0];   // [B, N, P]
    const int*   xi     = (const int*)  d_in[1];   // [B, P]
    const float* g      = (const float*)d_in[2];   // [N*N, N*N]
    const float* w      = (const float*)d_in[3];   // [N*N, 1]
    const float* alphas = (const float*)d_in[4];   // [1, T]

    float* out = (float*)d_out;
    float* Z = out;               // [B, N]   = 8192
    float* F = out + BB * NN;     // [N*N, T] = 688128

    k_main<<<TOTAL_K1, 512>>>(g, w, alphas, x, xi, F);
    k_z<<<BB, 256>>>(Z);
}